// round 4
// baseline (speedup 1.0000x reference)
#include <cuda_runtime.h>
#include <math.h>
#include <stdint.h>

// ---------------- problem constants ----------------
#define NB   32
#define IBND 103
#define HWD  256
#define RB   8
#define DIM  192
#define NTOK 256
#define NROW (NB*NTOK)      // 8192
#define NC   9
#define FFH  384
#define TAUV (0.07f + 1e-8f)

// ---------------- device scratch ----------------
__device__ __align__(256) float g_dw  [NB*RB*NTOK];
__device__ __align__(256) float g_tok [NROW*DIM];
__device__ __align__(256) float g_xb  [NROW*DIM];
__device__ __align__(256) float g_cat [NROW*200];
__device__ __align__(256) float g_keys[NROW*DIM];
__device__ __align__(256) float g_q   [NROW*DIM];
__device__ __align__(256) float g_v   [NROW*DIM];
__device__ __align__(256) float g_kv  [NB*DIM*DIM];
__device__ __align__(256) float g_ff  [NROW*FFH];
__device__ __align__(256) float g_s0  [NROW];
__device__ __align__(256) float g_s1  [NROW];

__device__ __forceinline__ float geluf(float x) {
    return 0.5f * x * (1.0f + erff(x * 0.70710678118654752440f));
}

__device__ __forceinline__ uint32_t to_tf32(float x) {
    uint32_t u;
    asm("cvt.rna.tf32.f32 %0, %1;" : "=r"(u) : "f"(x));
    return u;
}

__device__ __forceinline__ void mma_tf32(float* c, const uint32_t* a, const uint32_t* b) {
    asm volatile(
        "mma.sync.aligned.m16n8k8.row.col.f32.tf32.tf32.f32 "
        "{%0,%1,%2,%3}, {%4,%5,%6,%7}, {%8,%9}, {%0,%1,%2,%3};\n"
        : "+f"(c[0]), "+f"(c[1]), "+f"(c[2]), "+f"(c[3])
        : "r"(a[0]), "r"(a[1]), "r"(a[2]), "r"(a[3]), "r"(b[0]), "r"(b[1]));
}

// ============================================================
// Kernel 1: fused band-reduction + depthwise 16x16 patch conv (fp32 exact)
// ============================================================
__global__ void __launch_bounds__(512, 1) k_band_dw(
    const float* __restrict__ x, const float* __restrict__ band_w,
    const float* __restrict__ band_b, const float* __restrict__ dw_w,
    float* __restrict__ dwout)
{
    __shared__ float sdw[RB * 256];
    __shared__ float sband[RB * IBND];
    __shared__ float ssum[RB];
    __shared__ float xs[2][16 * 256];

    const int tid = threadIdx.x;
    const int b = blockIdx.x >> 4;
    const int i = blockIdx.x & 15;

    for (int l = tid; l < RB * 256; l += 512)  sdw[l]   = dw_w[l];
    for (int l = tid; l < RB * IBND; l += 512) sband[l] = band_w[l];
    __syncthreads();
    if (tid < RB) {
        float s = 0.f;
        for (int u = 0; u < 256; u++) s += sdw[tid * 256 + u];
        ssum[tid] = s;
    }

    const int w  = tid & 255;
    const int ch = tid >> 8;
    const int wq = w & 15;
    const int j  = w >> 4;

    float wt[4][16];
#pragma unroll
    for (int cl = 0; cl < 4; cl++)
#pragma unroll
        for (int p = 0; p < 16; p++)
            wt[cl][p] = sdw[((ch * 4 + cl) * 16 + p) * 16 + wq];
    __syncthreads();

    const int lin  = tid * 8;
    const int lrow = lin >> 8;
    const int lcol = lin & 255;

    float D[4] = {0.f, 0.f, 0.f, 0.f};
    float4 f0, f1;
    {
        const float* px = x + (((size_t)(b * IBND + 0) * HWD + i * 16 + lrow) * HWD + lcol);
        f0 = ((const float4*)px)[0];
        f1 = ((const float4*)px)[1];
    }

    for (int ib = 0; ib < IBND; ib++) {
        float* sdst = &xs[ib & 1][lrow * 256 + lcol];
        ((float4*)sdst)[0] = f0;
        ((float4*)sdst)[1] = f1;
        __syncthreads();

        if (ib + 1 < IBND) {
            const float* px = x + (((size_t)(b * IBND + ib + 1) * HWD + i * 16 + lrow) * HWD + lcol);
            f0 = ((const float4*)px)[0];
            f1 = ((const float4*)px)[1];
        }

        const float* xc = &xs[ib & 1][0];
        float s0 = 0.f, s1 = 0.f, s2 = 0.f, s3 = 0.f;
#pragma unroll
        for (int p = 0; p < 16; p++) {
            float xv = xc[p * 256 + w];
            s0 += xv * wt[0][p];
            s1 += xv * wt[1][p];
            s2 += xv * wt[2][p];
            s3 += xv * wt[3][p];
        }
        const int cb = ch * 4;
        D[0] += sband[(cb + 0) * IBND + ib] * s0;
        D[1] += sband[(cb + 1) * IBND + ib] * s1;
        D[2] += sband[(cb + 2) * IBND + ib] * s2;
        D[3] += sband[(cb + 3) * IBND + ib] * s3;
        __syncthreads();
    }

#pragma unroll
    for (int cl = 0; cl < 4; cl++) {
        float v = D[cl];
        v += __shfl_down_sync(0xffffffffu, v, 8, 16);
        v += __shfl_down_sync(0xffffffffu, v, 4, 16);
        v += __shfl_down_sync(0xffffffffu, v, 2, 16);
        v += __shfl_down_sync(0xffffffffu, v, 1, 16);
        if (wq == 0) {
            int c = ch * 4 + cl;
            dwout[((b * RB + c) * 16 + i) * 16 + j] = v + band_b[c] * ssum[c];
        }
    }
}

// ---------------- 192-thread block reduction helper ----------------
__device__ __forceinline__ float blk_sum_192(float v, float* sb) {
#pragma unroll
    for (int o = 16; o; o >>= 1) v += __shfl_down_sync(0xffffffffu, v, o);
    __syncthreads();
    if ((threadIdx.x & 31) == 0) sb[threadIdx.x >> 5] = v;
    __syncthreads();
    if (threadIdx.x == 0)
        sb[6] = sb[0] + sb[1] + sb[2] + sb[3] + sb[4] + sb[5];
    __syncthreads();
    return sb[6];
}

// ============================================================
// Kernel 2: pointwise 8->192 conv + LayerNorm -> tok, xb
// ============================================================
__global__ void k_pw_ln(const float* __restrict__ dw, const float* __restrict__ pw_w,
                        const float* __restrict__ lw, const float* __restrict__ lb,
                        float* __restrict__ tok, float* __restrict__ xbuf)
{
    const int row = blockIdx.x;
    const int b = row >> 8, n = row & 255;
    const int d = threadIdx.x;
    __shared__ float sdwv[RB];
    __shared__ float sb[8];
    if (d < RB) sdwv[d] = dw[((size_t)b * RB + d) * NTOK + n];
    __syncthreads();
    float t = 0.f;
#pragma unroll
    for (int c = 0; c < RB; c++) t += sdwv[c] * pw_w[d * RB + c];
    float mean = blk_sum_192(t, sb) * (1.f / 192.f);
    float dv = t - mean;
    float var = blk_sum_192(dv * dv, sb) * (1.f / 192.f);
    float o = dv * rsqrtf(var + 1e-5f) * lw[d] + lb[d];
    size_t idx = (size_t)row * DIM + d;
    tok[idx] = o;
    xbuf[idx] = o;
}

// ============================================================
// row stats: LN (mean, rstd) — warp per row
// ============================================================
__global__ void __launch_bounds__(256) k_lnstats(const float* __restrict__ xin,
                                                 float* __restrict__ s0, float* __restrict__ s1)
{
    const int warp = threadIdx.x >> 5, lane = threadIdx.x & 31;
    const int row = blockIdx.x * 8 + warp;
    const float* p = xin + (size_t)row * DIM;
    float v[6];
#pragma unroll
    for (int j = 0; j < 6; j++) v[j] = p[lane + j * 32];
    float s = v[0] + v[1] + v[2] + v[3] + v[4] + v[5];
#pragma unroll
    for (int o = 16; o; o >>= 1) s += __shfl_xor_sync(0xffffffffu, s, o);
    float mu = s * (1.f / 192.f);
    float q = 0.f;
#pragma unroll
    for (int j = 0; j < 6; j++) { float d = v[j] - mu; q += d * d; }
#pragma unroll
    for (int o = 16; o; o >>= 1) q += __shfl_xor_sync(0xffffffffu, q, o);
    if (lane == 0) { s0[row] = mu; s1[row] = rsqrtf(q * (1.f / 192.f) + 1e-5f); }
}

// ============================================================
// row stats: softmax (max, 1/sum(exp(x-max)))
// ============================================================
__global__ void __launch_bounds__(256) k_smstats(const float* __restrict__ xin,
                                                 float* __restrict__ s0, float* __restrict__ s1)
{
    const int warp = threadIdx.x >> 5, lane = threadIdx.x & 31;
    const int row = blockIdx.x * 8 + warp;
    const float* p = xin + (size_t)row * DIM;
    float v[6];
#pragma unroll
    for (int j = 0; j < 6; j++) v[j] = p[lane + j * 32];
    float m = v[0];
#pragma unroll
    for (int j = 1; j < 6; j++) m = fmaxf(m, v[j]);
#pragma unroll
    for (int o = 16; o; o >>= 1) m = fmaxf(m, __shfl_xor_sync(0xffffffffu, m, o));
    float e = 0.f;
#pragma unroll
    for (int j = 0; j < 6; j++) e += expf(v[j] - m);
#pragma unroll
    for (int o = 16; o; o >>= 1) e += __shfl_xor_sync(0xffffffffu, e, o);
    if (lane == 0) { s0[row] = m; s1[row] = 1.f / e; }
}

// ============================================================
// Fused router: h = gelu(tok@r1+b1); rl = h@r2+b2; top-2 per half;
// gates; prototype mix -> cat[row,200].  Exact fp32 (protects top-k).
// Block = 64 rows, 256 threads. grid = NROW/64 = 128.
// ============================================================
__global__ void __launch_bounds__(256) k_router(
    const float* __restrict__ tok,
    const float* __restrict__ r1_w, const float* __restrict__ r1_b,
    const float* __restrict__ r2_w, const float* __restrict__ r2_b,
    const float* __restrict__ spec_proto, const float* __restrict__ spat_proto,
    float* __restrict__ cat)
{
    __shared__ float As[16][68];    // tok tile transposed [k][m]
    __shared__ float Bs[16][132];   // r1 tile [k][128] / reused for r2 tiles [k][48]
    __shared__ float Hs[64][129];   // gelu(h) 64x128

    const int tid = threadIdx.x;
    const int m0 = blockIdx.x * 64;
    const int ty = tid >> 4, tx = tid & 15;     // phase-1 mapping

    // ---------- phase 1: H = gelu(tok[64,192] @ r1_w[192,128] + b1) ----------
    float acc[4][8];
#pragma unroll
    for (int i = 0; i < 4; i++)
#pragma unroll
        for (int c = 0; c < 8; c++) acc[i][c] = 0.f;

    for (int k0 = 0; k0 < DIM; k0 += 16) {
        {   // A tile: 64x16, thread loads 1 float4
            int am = tid >> 2, ak = (tid & 3) * 4;
            float4 t = *(const float4*)(tok + (size_t)(m0 + am) * DIM + k0 + ak);
            As[ak + 0][am] = t.x; As[ak + 1][am] = t.y;
            As[ak + 2][am] = t.z; As[ak + 3][am] = t.w;
        }
        {   // B tile: 16x128, thread loads 2 float4
            int bk = tid >> 4, bn = (tid & 15) * 8;
            const float* src = r1_w + (size_t)(k0 + bk) * 128 + bn;
            float4 t0 = *(const float4*)(src);
            float4 t1 = *(const float4*)(src + 4);
            *(float4*)&Bs[bk][bn] = t0;
            *(float4*)&Bs[bk][bn + 4] = t1;
        }
        __syncthreads();
#pragma unroll
        for (int kk = 0; kk < 16; kk++) {
            float4 a4 = *(const float4*)&As[kk][ty * 4];
            float am4[4] = {a4.x, a4.y, a4.z, a4.w};
            float bm[8];
#pragma unroll
            for (int c = 0; c < 8; c++) bm[c] = Bs[kk][tx + 16 * c];   // strided cols: conflict-free
#pragma unroll
            for (int i = 0; i < 4; i++)
#pragma unroll
                for (int c = 0; c < 8; c++) acc[i][c] += am4[i] * bm[c];
        }
        __syncthreads();
    }
#pragma unroll
    for (int i = 0; i < 4; i++)
#pragma unroll
        for (int c = 0; c < 8; c++) {
            int col = tx + 16 * c;
            Hs[ty * 4 + i][col] = geluf(acc[i][c] + r1_b[col]);
        }

    // ---------- phase 2: rl = H @ r2_w[128,48] + b2 (per-thread 12 cols) ----------
    const int rowp = tid >> 2;        // 0..63
    const int jj   = tid & 3;         // 0..3 -> cols jj*12..jj*12+11
    float acc2[12];
#pragma unroll
    for (int c = 0; c < 12; c++) acc2[c] = 0.f;

    for (int kt = 0; kt < 8; kt++) {
        __syncthreads();              // prior reads of Bs / Hs writes settled
        for (int l = tid; l < 768; l += 256) {
            int k = l / 48, n = l - k * 48;
            Bs[k][n] = r2_w[(size_t)(kt * 16 + k) * 48 + n];
        }
        __syncthreads();
#pragma unroll
        for (int kk = 0; kk < 16; kk++) {
            float hv = Hs[rowp][kt * 16 + kk];
#pragma unroll
            for (int c = 0; c < 12; c++) acc2[c] += hv * Bs[kk][jj * 12 + c];
        }
    }
#pragma unroll
    for (int c = 0; c < 12; c++) acc2[c] += r2_b[jj * 12 + c];

    // ---------- phase 3: local top-2 of 12, merge pairwise via shuffle ----------
    const int boff = (jj & 1) * 12;   // local index base within the 24-half
    float m1 = -1e30f, m2 = -1e30f; int i1 = 0, i2 = 0;
#pragma unroll
    for (int c = 0; c < 12; c++) {
        float vv = acc2[c]; int idx = boff + c;
        if (vv > m1) { m2 = m1; i2 = i1; m1 = vv; i1 = idx; }
        else if (vv > m2) { m2 = vv; i2 = idx; }
    }
    const unsigned FULL = 0xffffffffu;
    float om1 = __shfl_xor_sync(FULL, m1, 1);
    float om2 = __shfl_xor_sync(FULL, m2, 1);
    int   oi1 = __shfl_xor_sync(FULL, i1, 1);
    int   oi2 = __shfl_xor_sync(FULL, i2, 1);
    float am1, am2, bm1, bm2; int ai1, ai2, bi1, bi2;
    if ((jj & 1) == 0) { am1 = m1;  ai1 = i1;  am2 = m2;  ai2 = i2;  bm1 = om1; bi1 = oi1; bm2 = om2; bi2 = oi2; }
    else               { am1 = om1; ai1 = oi1; am2 = om2; ai2 = oi2; bm1 = m1;  bi1 = i1;  bm2 = m2;  bi2 = i2; }
    float M1, M2; int I1, I2;
    if (am1 >= bm1) {
        M1 = am1; I1 = ai1;
        if (am2 >= bm1) { M2 = am2; I2 = ai2; } else { M2 = bm1; I2 = bi1; }
    } else {
        M1 = bm1; I1 = bi1;
        if (am1 >= bm2) { M2 = am1; I2 = ai1; } else { M2 = bm2; I2 = bi2; }
    }
    float e  = expf((M2 - M1) / TAUV);
    float g1 = 1.f / (1.f + e);
    float g2 = e * g1;

    // broadcast spec gates (from lane base+0) and spat gates (from base+2)
    const int lane = tid & 31;
    const int lb = lane & ~3;
    float sgA = __shfl_sync(FULL, g1, lb + 0);
    float sgB = __shfl_sync(FULL, g2, lb + 0);
    int   siA = __shfl_sync(FULL, I1, lb + 0);
    int   siB = __shfl_sync(FULL, I2, lb + 0);
    float pgA = __shfl_sync(FULL, g1, lb + 2);
    float pgB = __shfl_sync(FULL, g2, lb + 2);
    int   piA = __shfl_sync(FULL, I1, lb + 2);
    int   piB = __shfl_sync(FULL, I2, lb + 2);

    // ---------- phase 4: write cat[row, 200] ----------
    float* crow = cat + (size_t)(m0 + rowp) * 200;
    const int c0 = jj * 50;
    for (int c = c0; c < c0 + 50; c++) {
        float val;
        if (c < 8)
            val = sgA * spec_proto[siA * RB + c] + sgB * spec_proto[siB * RB + c];
        else {
            int cc = c - 8;
            val = pgA * spat_proto[piA * DIM + cc] + pgB * spat_proto[piB * DIM + cc];
        }
        crow[c] = val;
    }
}

// ============================================================
// tf32 tensor-core GEMM v3: double-buffered smem + register prefetch.
// BM=128, BN=64, BK=32, 256 thr = 8 warps (4m x 2n). ONE sync per K-tile.
// Dynamic smem: 2 A buffers (5120 fl) + 2 B buffers (2176 fl) = 58368 B.
// TRANSA=0: A MxK row-major.  TRANSA=1: A KxM row-major (A^T @ B).
// ATR: 0 none, 1 LayerNorm(s0=mean,s1=rstd,tw/tb), 2 softmax(s0=max,s1=1/sum)
// EPI: 0 store, 1 +bias, 2 gelu(+bias), 3 C+=acc*scale, 4 C+=(acc+bias)*scale
// Column split: blockIdx.x >= xsplit uses B2/C2 (merged q/v launch).
// ============================================================
#define SA0 40
#define SA1 132
#define SBP 68
#define A_BUF 5120
#define B_OFF 10240
#define B_BUF 2176
#define MMA3_SMEM ((B_OFF + 2 * B_BUF) * 4)

template <int EPI, int TRANSA, int ATR>
__global__ void __launch_bounds__(256) mma3(
    const float* __restrict__ A, const float* __restrict__ B, const float* __restrict__ B2,
    float* __restrict__ C, float* __restrict__ C2, int xsplit,
    const float* __restrict__ bias, const float* __restrict__ scale,
    const float* __restrict__ s0, const float* __restrict__ s1,
    const float* __restrict__ tw, const float* __restrict__ tb,
    int M, int N, int K, long sAs, long sBs, long sCs, int statStride)
{
    extern __shared__ float dyn[];

    const long bz = blockIdx.z;
    const float* Ap = A + bz * sAs;
    const float* Bp = (blockIdx.x < xsplit ? B : B2) + bz * sBs;
    float*       Cp = (blockIdx.x < xsplit ? C : C2) + bz * sCs;
    const int m0 = blockIdx.y * 128;
    const int n0 = (blockIdx.x % xsplit) * 64;
    const int tid = threadIdx.x;
    const int warp = tid >> 5, lane = tid & 31;
    const int grp = lane >> 2, tig = lane & 3;
    const int wm = warp >> 1, wn = warp & 1;

    float acc[2][4][4];
#pragma unroll
    for (int mt = 0; mt < 2; mt++)
#pragma unroll
        for (int nt = 0; nt < 4; nt++)
#pragma unroll
            for (int e = 0; e < 4; e++) acc[mt][nt][e] = 0.f;

    float4 apre[4];
    float4 bpre[2];

    auto fetchA = [&](int k0) {
#pragma unroll
        for (int it = 0; it < 4; it++) {
            int id = tid + it * 256;
            float4 t = make_float4(0.f, 0.f, 0.f, 0.f);
            if (TRANSA == 0) {
                int m = id >> 3, k4 = (id & 7) * 4;
                int gm = m0 + m, gk = k0 + k4;
                if (gm < M && gk < K) {
                    if (gk + 3 < K) t = *(const float4*)(Ap + (size_t)gm * K + gk);
                    else {
                        float* tp = (float*)&t;
#pragma unroll
                        for (int u = 0; u < 4; u++)
                            if (gk + u < K) tp[u] = Ap[(size_t)gm * K + gk + u];
                    }
                }
                if (ATR == 1 && gm < M) {
                    int sr = (int)bz * statStride + gm;
                    float mu = s0[sr], rs = s1[sr];
                    float4 w4 = make_float4(0.f, 0.f, 0.f, 0.f);
                    float4 b4 = make_float4(0.f, 0.f, 0.f, 0.f);
                    if (gk + 3 < K) { w4 = *(const float4*)(tw + gk); b4 = *(const float4*)(tb + gk); }
                    t.x = (t.x - mu) * rs * w4.x + b4.x;
                    t.y = (t.y - mu) * rs * w4.y + b4.y;
                    t.z = (t.z - mu) * rs * w4.z + b4.z;
                    t.w = (t.w - mu) * rs * w4.w + b4.w;
                }
                if (ATR == 2 && gm < M) {
                    int sr = (int)bz * statStride + gm;
                    float mx = s0[sr], iv = s1[sr];
                    t.x = expf(t.x - mx) * iv;
                    t.y = expf(t.y - mx) * iv;
                    t.z = expf(t.z - mx) * iv;
                    t.w = expf(t.w - mx) * iv;
                }
            } else {
                int k = id >> 5, m4 = (id & 31) * 4;
                int gk = k0 + k, gm = m0 + m4;
                if (gk < K && gm < M) {
                    if (gm + 3 < M) t = *(const float4*)(Ap + (size_t)gk * M + gm);
                    else {
                        float* tp = (float*)&t;
#pragma unroll
                        for (int u = 0; u < 4; u++)
                            if (gm + u < M) tp[u] = Ap[(size_t)gk * M + gm + u];
                    }
                }
            }
            apre[it] = t;
        }
    };
    auto fetchB = [&](int k0) {
#pragma unroll
        for (int it = 0; it < 2; it++) {
            int id = tid + it * 256;
            int k = id >> 4, n4 = (id & 15) * 4;
            int gk = k0 + k, gn = n0 + n4;
            float4 t = make_float4(0.f, 0.f, 0.f, 0.f);
            if (gk < K) {
                if (gn + 3 < N) t = *(const float4*)(Bp + (size_t)gk * N + gn);
                else {
                    float* tp = (float*)&t;
#pragma unroll
                    for (int u = 0; u < 4; u++)
                        if (gn + u < N) tp[u] = Bp[(size_t)gk * N + gn + u];
                }
            }
            bpre[it] = t;
        }
    };
    auto storeA = [&](int buf) {
        float* sA = dyn + buf * A_BUF;
#pragma unroll
        for (int it = 0; it < 4; it++) {
            int id = tid + it * 256;
            uint4 c;
            c.x = to_tf32(apre[it].x); c.y = to_tf32(apre[it].y);
            c.z = to_tf32(apre[it].z); c.w = to_tf32(apre[it].w);
            if (TRANSA == 0) {
                int m = id >> 3, k4 = (id & 7) * 4;
                *(uint4*)&sA[m * SA0 + k4] = c;
            } else {
                int k = id >> 5, m4 = (id & 31) * 4;
                *(uint4*)&sA[k * SA1 + m4] = c;
            }
        }
    };
    auto storeB = [&](int buf) {
        float* sB = dyn + B_OFF + buf * B_BUF;
#pragma unroll
        for (int it = 0; it < 2; it++) {
            int id = tid + it * 256;
            int k = id >> 4, n4 = (id & 15) * 4;
            uint4 c;
            c.x = to_tf32(bpre[it].x); c.y = to_tf32(bpre[it].y);
            c.z = to_tf32(bpre[it].z); c.w = to_tf32(bpre[it].w);
            *(uint4*)&sB[k * SBP + n4] = c;
        }
    };

    fetchA(0); fetchB(0);
    storeA(0); storeB(0);
    __syncthreads();

    const int T = (K + 31) / 32;
    for (int t = 0; ; t++) {
        const bool more = (t + 1) < T;
        if (more) { fetchA((t + 1) * 32); fetchB((t + 1) * 32); }

        const float* sA = dyn + (t & 1) * A_BUF;
        const float* sB = dyn + B_OFF + (t & 1) * B_BUF;
#pragma unroll
        for (int ks = 0; ks < 4; ks++) {
            uint32_t a[2][4], b[4][2];
            const int kr = ks * 8 + tig * 2;
#pragma unroll
            for (int mt = 0; mt < 2; mt++) {
                int mr = wm * 32 + mt * 16 + grp;
                if (TRANSA == 0) {
                    float2 p0 = *(const float2*)&sA[mr * SA0 + kr];
                    float2 p1 = *(const float2*)&sA[(mr + 8) * SA0 + kr];
                    a[mt][0] = __float_as_uint(p0.x);
                    a[mt][1] = __float_as_uint(p1.x);
                    a[mt][2] = __float_as_uint(p0.y);
                    a[mt][3] = __float_as_uint(p1.y);
                } else {
                    a[mt][0] = __float_as_uint(sA[kr * SA1 + mr]);
                    a[mt][2] = __float_as_uint(sA[(kr + 1) * SA1 + mr]);
                    a[mt][1] = __float_as_uint(sA[kr * SA1 + mr + 8]);
                    a[mt][3] = __float_as_uint(sA[(kr + 1) * SA1 + mr + 8]);
                }
            }
#pragma unroll
            for (int nt = 0; nt < 4; nt++) {
                int nc = wn * 32 + nt * 8 + grp;
                b[nt][0] = __float_as_uint(sB[kr * SBP + nc]);
                b[nt][1] = __float_as_uint(sB[(kr + 1) * SBP + nc]);
            }
#pragma unroll
            for (int mt = 0; mt < 2; mt++)
#pragma unroll
                for (int nt = 0; nt < 4; nt++)
                    mma_tf32(acc[mt][nt], a[mt], b[nt]);
        }

        if (!more) break;
        storeA((t + 1) & 1); storeB((t + 1) & 1);   // other buffer: no pre-store sync needed
        __syncthreads();
    }

    // ---------- epilogue ----------
#pragma unroll
    for (int mt = 0; mt < 2; mt++) {
        int r0 = m0 + wm * 32 + mt * 16 + grp;
#pragma unroll
        for (int nt = 0; nt < 4; nt++) {
            int c0 = n0 + wn * 32 + nt * 8 + tig * 2;
            const float* ap = acc[mt][nt];
#pragma unroll
            for (int e = 0; e < 4; e++) {
                int row = r0 + (e >= 2 ? 8 : 0);
                int col = c0 + (e & 1);
                if (row >= M || col >= N) continue;
                float v = ap[e];
                size_t idx = (size_t)row * N + col;
                if (EPI == 0)      Cp[idx] = v;
                else if (EPI == 1) Cp[idx] = v + bias[col];
                else if (EPI == 2) Cp[idx] = geluf(v + bias[col]);
                else if (EPI == 3) Cp[idx] = Cp[idx] + v * scale[col];
                else if (EPI == 4) Cp[idx] = Cp[idx] + (v + bias[col]) * scale[col];
            }
        }
    }
}

// ============================================================
// final: feat = LN(mean_n xb), out = feat @ head_w + head_b
// ============================================================
__global__ void k_final(const float* __restrict__ xb,
                        const float* __restrict__ lw, const float* __restrict__ lb,
                        const float* __restrict__ hw, const float* __restrict__ hb,
                        float* __restrict__ out)
{
    const int b = blockIdx.x, d = threadIdx.x;
    __shared__ float sfeat[DIM];
    __shared__ float sb[8];
    const float* base = xb + (size_t)b * NTOK * DIM;
    float acc = 0.f;
    for (int n = 0; n < NTOK; n++) acc += base[n * DIM + d];
    float m = acc * (1.f / 256.f);
    float mean = blk_sum_192(m, sb) * (1.f / 192.f);
    float dv = m - mean;
    float var = blk_sum_192(dv * dv, sb) * (1.f / 192.f);
    sfeat[d] = dv * rsqrtf(var + 1e-5f) * lw[d] + lb[d];
    __syncthreads();
    if (d < NC) {
        float o = hb[d];
        for (int e = 0; e < DIM; e++) o += sfeat[e] * hw[e * NC + d];
        out[b * NC + d] = o;
    }
}

// ============================================================
extern "C" void kernel_launch(void* const* d_in, const int* in_sizes, int n_in,
                              void* d_out, int out_size)
{
    const float* x        = (const float*)d_in[0];
    const float* band_w   = (const float*)d_in[1];
    const float* band_b   = (const float*)d_in[2];
    const float* dw_w     = (const float*)d_in[3];
    const float* pw_w     = (const float*)d_in[4];
    const float* pe_ln_w  = (const float*)d_in[5];
    const float* pe_ln_b  = (const float*)d_in[6];
    const float* spec_pr  = (const float*)d_in[7];
    const float* spat_pr  = (const float*)d_in[8];
    const float* r1_w     = (const float*)d_in[9];
    const float* r1_b     = (const float*)d_in[10];
    const float* r2_w     = (const float*)d_in[11];
    const float* r2_b     = (const float*)d_in[12];
    const float* key_w    = (const float*)d_in[13];
    const float* pos_bias = (const float*)d_in[14];
    const float* bln_w    = (const float*)d_in[15];
    const float* bln_b    = (const float*)d_in[16];
    const float* bq_w     = (const float*)d_in[17];
    const float* bv_w     = (const float*)d_in[18];
    const float* bf1_w    = (const float*)d_in[19];
    const float* bf1_b    = (const float*)d_in[20];
    const float* bf2_w    = (const float*)d_in[21];
    const float* bf2_b    = (const float*)d_in[22];
    const float* bg1      = (const float*)d_in[23];
    const float* bg2      = (const float*)d_in[24];
    const float* fin_ln_w = (const float*)d_in[25];
    const float* fin_ln_b = (const float*)d_in[26];
    const float* head_w   = (const float*)d_in[27];
    const float* head_b   = (const float*)d_in[28];
    float* out = (float*)d_out;

    float *dw, *tok, *xb, *cat, *keys, *q, *v, *kv, *ff, *st0, *st1;
    cudaGetSymbolAddress((void**)&dw,   g_dw);
    cudaGetSymbolAddress((void**)&tok,  g_tok);
    cudaGetSymbolAddress((void**)&xb,   g_xb);
    cudaGetSymbolAddress((void**)&cat,  g_cat);
    cudaGetSymbolAddress((void**)&keys, g_keys);
    cudaGetSymbolAddress((void**)&q,    g_q);
    cudaGetSymbolAddress((void**)&v,    g_v);
    cudaGetSymbolAddress((void**)&kv,   g_kv);
    cudaGetSymbolAddress((void**)&ff,   g_ff);
    cudaGetSymbolAddress((void**)&st0,  g_s0);
    cudaGetSymbolAddress((void**)&st1,  g_s1);

    // opt-in to 58KB dynamic smem (idempotent; errors are harmless repeats)
    cudaFuncSetAttribute(mma3<1,0,0>, cudaFuncAttributeMaxDynamicSharedMemorySize, MMA3_SMEM);
    cudaFuncSetAttribute(mma3<0,0,1>, cudaFuncAttributeMaxDynamicSharedMemorySize, MMA3_SMEM);
    cudaFuncSetAttribute(mma3<0,1,0>, cudaFuncAttributeMaxDynamicSharedMemorySize, MMA3_SMEM);
    cudaFuncSetAttribute(mma3<3,0,2>, cudaFuncAttributeMaxDynamicSharedMemorySize, MMA3_SMEM);
    cudaFuncSetAttribute(mma3<2,0,1>, cudaFuncAttributeMaxDynamicSharedMemorySize, MMA3_SMEM);
    cudaFuncSetAttribute(mma3<4,0,0>, cudaFuncAttributeMaxDynamicSharedMemorySize, MMA3_SMEM);

    const int BIG = 1 << 20;
    const long sTok = (long)NTOK * DIM;
    const long sKV  = (long)DIM * DIM;

    // 1. fused band + depthwise conv
    k_band_dw<<<NB * 16, 512>>>(x, band_w, band_b, dw_w, dw);
    // 2. pointwise conv + LN -> tok, xb
    k_pw_ln<<<NROW, DIM>>>(dw, pw_w, pe_ln_w, pe_ln_b, tok, xb);
    // 3. fused router (exact fp32 MLP + top-2 + gates + mix) -> cat
    k_router<<<NROW / 64, 256>>>(tok, r1_w, r1_b, r2_w, r2_b, spec_pr, spat_pr, cat);
    // 4. keys = cat @ key_w + pos_bias  (tf32)
    mma3<1, 0, 0><<<dim3(3, 64), 256, MMA3_SMEM>>>(cat, key_w, nullptr, keys, nullptr, BIG,
                                        pos_bias, nullptr, nullptr, nullptr, nullptr, nullptr,
                                        NROW, DIM, 200, 0, 0, 0, 0);

    for (int i = 0; i < 3; i++) {
        const float* lwi = bln_w + i * DIM;
        const float* lbi = bln_b + i * DIM;
        // LN stats of xb, merged q+v GEMM with fused LN on A
        k_lnstats<<<NROW / 8, 256>>>(xb, st0, st1);
        mma3<0, 0, 1><<<dim3(6, 64), 256, MMA3_SMEM>>>(xb, bq_w + (size_t)i * DIM * DIM, bv_w + (size_t)i * DIM * DIM,
                                            q, v, 3, nullptr, nullptr, st0, st1, lwi, lbi,
                                            NROW, DIM, DIM, 0, 0, 0, 0);
        // softmax stats of q
        k_smstats<<<NROW / 8, 256>>>(q, st0, st1);
        // KV[b] = keys[b]^T @ v[b]
        mma3<0, 1, 0><<<dim3(3, 2, NB), 256, MMA3_SMEM>>>(keys, v, nullptr, kv, nullptr, BIG,
                                               nullptr, nullptr, nullptr, nullptr, nullptr, nullptr,
                                               DIM, DIM, NTOK, sTok, sTok, sKV, 0);
        // xb += (softmax(q) @ KV) * g1   (softmax fused into A-load)
        mma3<3, 0, 2><<<dim3(3, 2, NB), 256, MMA3_SMEM>>>(q, kv, nullptr, xb, nullptr, BIG,
                                               nullptr, bg1 + i * DIM, st0, st1, nullptr, nullptr,
                                               NTOK, DIM, DIM, sTok, sKV, sTok, NTOK);
        // FFN: LN stats, f1 with fused LN + gelu, f2 with residual
        k_lnstats<<<NROW / 8, 256>>>(xb, st0, st1);
        mma3<2, 0, 1><<<dim3(6, 64), 256, MMA3_SMEM>>>(xb, bf1_w + (size_t)i * DIM * FFH, nullptr,
                                            ff, nullptr, BIG, bf1_b + i * FFH, nullptr, st0, st1, lwi, lbi,
                                            NROW, FFH, DIM, 0, 0, 0, 0);
        mma3<4, 0, 0><<<dim3(3, 64), 256, MMA3_SMEM>>>(ff, bf2_w + (size_t)i * FFH * DIM, nullptr,
                                            xb, nullptr, BIG, bf2_b + i * DIM, bg2 + i * DIM,
                                            nullptr, nullptr, nullptr, nullptr,
                                            NROW, DIM, FFH, 0, 0, 0, 0);
    }

    // final pooling + LN + head
    k_final<<<NB, DIM>>>(xb, fin_ln_w, fin_ln_b, head_w, head_b, out);

    (void)in_sizes; (void)n_in; (void)out_size;
}